// round 1
// baseline (speedup 1.0000x reference)
#include <cuda_runtime.h>
#include <cstdint>

// Problem constants
#define BB 4
#define HH 512
#define WW 1024
#define HW (HH*WW)          // 524288 pixels per batch image
#define NI 8                // instances 1..8
#define NBINS 65536
#define WBIN (2.0f/(float)NBINS)
#define BSCALE ((float)NBINS/2.0f)   // 32768

// ---------------- device scratch (no allocations allowed) ----------------
// hist layout: [n][b][pos][bin]  index = ((n*BB+b)*2 + pos)*NBINS + bin
__device__ unsigned int g_hist[NI*BB*2*NBINS];         // 16 MB
__device__ float g_sums[BB][NI][5];                    // cnt, sum_e0, sum_e1, sum_pp0, sum_pp1
__device__ float g_bg[BB][2];                          // bg_cnt, bg_seed_sq
__device__ float g_stats[BB][NI][8];                   // c0,c1,psig0,psig1,pp0,pp1,inv_safe,present
__device__ float g_sl[BB][NI];                         // sigma-loss numerator sums
__device__ float g_fg[BB][NI];                         // seed fg numerator sums
__device__ float g_lov[BB][NI];                        // lovasz per row

// ---------------- zero scratch ----------------
__global__ void zero_kernel() {
    long i = (long)blockIdx.x * blockDim.x + threadIdx.x;
    long stride = (long)gridDim.x * blockDim.x;
    const long total = (long)NI*BB*2*NBINS;
    for (long k = i; k < total; k += stride) g_hist[k] = 0u;
    if (i < BB*NI*5) ((float*)g_sums)[i] = 0.0f;
    if (i < BB*2)    ((float*)g_bg)[i]   = 0.0f;
    if (i < BB*NI) { ((float*)g_sl)[i] = 0.0f; ((float*)g_fg)[i] = 0.0f; }
}

__device__ __forceinline__ float sigmoidf_fast(float x) {
    return 1.0f / (1.0f + __expf(-x));
}

// ---------------- pass 1: masked per-instance sums + bg seed stats ----------------
#define P1_TPB 256
#define P1_PPT 32   // pixels per thread -> 8192 per block -> 64 blocks per batch

__global__ __launch_bounds__(P1_TPB)
void pass1_kernel(const float* __restrict__ xv, const float* __restrict__ xs,
                  const float* __restrict__ xseed, const int* __restrict__ t) {
    const int b = blockIdx.y;
    const int p0 = blockIdx.x * (P1_TPB * P1_PPT) + threadIdx.x;
    const float* xv0 = xv + (long)b*2*HW;
    const float* xv1 = xv0 + HW;
    const float* xs0 = xs + (long)b*2*HW;
    const float* xs1 = xs0 + HW;
    const float* sdp = xseed + (long)b*HW;
    const int*   tp  = t + (long)b*HW;

    float acc[NI*5];
    #pragma unroll
    for (int i = 0; i < NI*5; i++) acc[i] = 0.0f;
    float bgc = 0.0f, bgs = 0.0f;

    #pragma unroll 4
    for (int i = 0; i < P1_PPT; i++) {
        int p = p0 + i * P1_TPB;
        int tv = tp[p];
        float e0 = tanhf(xv0[p]) + (float)(p >> 10) * (1.0f/1024.0f);
        float e1 = tanhf(xv1[p]) + (float)(p & 1023) * (1.0f/1024.0f);
        float q0 = xs0[p], q1 = xs1[p];
        float sd = sigmoidf_fast(sdp[p]);
        float isbg = (tv == 0) ? 1.0f : 0.0f;
        bgc += isbg;
        bgs += isbg * sd * sd;
        #pragma unroll
        for (int n = 0; n < NI; n++) {
            float m = (tv == n + 1) ? 1.0f : 0.0f;
            acc[n*5+0] += m;
            acc[n*5+1] += m * e0;
            acc[n*5+2] += m * e1;
            acc[n*5+3] += m * q0;
            acc[n*5+4] += m * q1;
        }
    }
    // warp reduction
    #pragma unroll
    for (int off = 16; off; off >>= 1) {
        #pragma unroll
        for (int i = 0; i < NI*5; i++)
            acc[i] += __shfl_down_sync(0xffffffffu, acc[i], off);
        bgc += __shfl_down_sync(0xffffffffu, bgc, off);
        bgs += __shfl_down_sync(0xffffffffu, bgs, off);
    }
    __shared__ float s_acc[NI*5 + 2];
    if (threadIdx.x < NI*5 + 2) s_acc[threadIdx.x] = 0.0f;
    __syncthreads();
    if ((threadIdx.x & 31) == 0) {
        #pragma unroll
        for (int i = 0; i < NI*5; i++) atomicAdd(&s_acc[i], acc[i]);
        atomicAdd(&s_acc[NI*5 + 0], bgc);
        atomicAdd(&s_acc[NI*5 + 1], bgs);
    }
    __syncthreads();
    if (threadIdx.x < NI*5)
        atomicAdd(&((float*)g_sums)[b*NI*5 + threadIdx.x], s_acc[threadIdx.x]);
    else if (threadIdx.x < NI*5 + 2)
        atomicAdd(&((float*)g_bg)[b*2 + (threadIdx.x - NI*5)], s_acc[threadIdx.x]);
}

// ---------------- finalize per-instance stats ----------------
__global__ void finalize_stats_kernel() {
    int i = threadIdx.x;
    if (i >= BB*NI) return;
    int b = i / NI, n = i % NI;
    float cnt  = g_sums[b][n][0];
    float safe = fmaxf(cnt, 1.0f);
    float inv  = 1.0f / safe;
    float c0  = g_sums[b][n][1] * inv;
    float c1  = g_sums[b][n][2] * inv;
    float pp0 = g_sums[b][n][3] * inv;
    float pp1 = g_sums[b][n][4] * inv;
    g_stats[b][n][0] = c0;
    g_stats[b][n][1] = c1;
    g_stats[b][n][2] = expf(10.0f * pp0);
    g_stats[b][n][3] = expf(10.0f * pp1);
    g_stats[b][n][4] = pp0;
    g_stats[b][n][5] = pp1;
    g_stats[b][n][6] = inv;
    g_stats[b][n][7] = (cnt > 0.0f) ? 1.0f : 0.0f;
}

// ---------------- pass 2: gauss, error histograms, sigma & seed partials ----------------
#define P2_TPB 256
#define P2_PPT 8   // 2048 pixels per block -> 256 blocks per batch

__global__ __launch_bounds__(P2_TPB)
void pass2_kernel(const float* __restrict__ xv, const float* __restrict__ xs,
                  const float* __restrict__ xseed, const int* __restrict__ t) {
    const int b = blockIdx.y;
    __shared__ float sc0[NI], sc1[NI], sps0[NI], sps1[NI], spp0[NI], spp1[NI];
    __shared__ float s_out[2*NI];
    if (threadIdx.x < NI) {
        int n = threadIdx.x;
        sc0[n]  = g_stats[b][n][0];
        sc1[n]  = g_stats[b][n][1];
        sps0[n] = g_stats[b][n][2];
        sps1[n] = g_stats[b][n][3];
        spp0[n] = g_stats[b][n][4];
        spp1[n] = g_stats[b][n][5];
    }
    if (threadIdx.x < 2*NI) s_out[threadIdx.x] = 0.0f;
    __syncthreads();

    const float* xv0 = xv + (long)b*2*HW;
    const float* xv1 = xv0 + HW;
    const float* xs0 = xs + (long)b*2*HW;
    const float* xs1 = xs0 + HW;
    const float* sdp = xseed + (long)b*HW;
    const int*   tp  = t + (long)b*HW;

    float tsl[NI], tfg[NI];
    #pragma unroll
    for (int n = 0; n < NI; n++) { tsl[n] = 0.0f; tfg[n] = 0.0f; }

    const int p0 = blockIdx.x * (P2_TPB * P2_PPT) + threadIdx.x;
    for (int i = 0; i < P2_PPT; i++) {
        int p = p0 + i * P2_TPB;
        int tv = tp[p];
        float e0 = tanhf(xv0[p]) + (float)(p >> 10) * (1.0f/1024.0f);
        float e1 = tanhf(xv1[p]) + (float)(p & 1023) * (1.0f/1024.0f);
        float q0 = xs0[p], q1 = xs1[p];
        float sd = sigmoidf_fast(sdp[p]);
        #pragma unroll
        for (int n = 0; n < NI; n++) {
            float d0 = e0 - sc0[n];
            float d1 = e1 - sc1[n];
            float dist = d0*d0*sps0[n] + d1*d1*sps1[n];
            float g = __expf(-0.5f * dist);
            bool pos = (tv == n + 1);
            float err = pos ? (2.0f - 2.0f*g) : (2.0f*g);
            int bin = (int)(err * BSCALE);
            bin = min(bin, NBINS - 1);
            unsigned int* hptr = g_hist + ((long)((n*BB + b)*2 + (pos ? 1 : 0)))*NBINS + bin;
            atomicAdd(hptr, 1u);
            float m = pos ? 1.0f : 0.0f;
            float dd0 = q0 - spp0[n], dd1 = q1 - spp1[n];
            tsl[n] += m * (dd0*dd0 + dd1*dd1);
            float fgd = sd - g;
            tfg[n] += m * fgd * fgd;
        }
    }
    // warp reduce 16 values
    #pragma unroll
    for (int off = 16; off; off >>= 1) {
        #pragma unroll
        for (int n = 0; n < NI; n++) {
            tsl[n] += __shfl_down_sync(0xffffffffu, tsl[n], off);
            tfg[n] += __shfl_down_sync(0xffffffffu, tfg[n], off);
        }
    }
    if ((threadIdx.x & 31) == 0) {
        #pragma unroll
        for (int n = 0; n < NI; n++) {
            atomicAdd(&s_out[n],      tsl[n]);
            atomicAdd(&s_out[NI + n], tfg[n]);
        }
    }
    __syncthreads();
    if (threadIdx.x < NI)
        atomicAdd(&g_sl[b][threadIdx.x], s_out[threadIdx.x]);
    else if (threadIdx.x < 2*NI)
        atomicAdd(&g_fg[b][threadIdx.x - NI], s_out[threadIdx.x]);
}

// ---------------- pass 3: histogram suffix scan -> lovasz per row ----------------
#define P3_TPB 512
#define P3_BPT (NBINS / P3_TPB)   // 128 bins per thread

__global__ __launch_bounds__(P3_TPB)
void pass3_kernel() {
    const int row = blockIdx.x;        // 0..31
    const int n = row >> 2;
    const int b = row & 3;
    const unsigned int* hp = g_hist + ((long)((n*BB + b)*2 + 1))*NBINS;
    const unsigned int* hn = g_hist + ((long)((n*BB + b)*2 + 0))*NBINS;
    const int j = threadIdx.x;
    const int lo = j * P3_BPT;

    unsigned int lp = 0u, ln = 0u;
    for (int k = 0; k < P3_BPT; k++) { lp += hp[lo + k]; ln += hn[lo + k]; }

    __shared__ float sp[P3_TPB], sn[P3_TPB];
    __shared__ float ep[P3_TPB], en[P3_TPB];   // exclusive suffix sums
    __shared__ float sG, sD0, s_jacsum;
    sp[j] = (float)lp;
    sn[j] = (float)ln;
    if (j == 0) s_jacsum = 0.0f;
    __syncthreads();
    if (j == 0) {
        float ap = 0.0f, an = 0.0f;
        for (int k = P3_TPB - 1; k >= 0; k--) {
            ep[k] = ap; en[k] = an;
            ap += sp[k]; an += sn[k];
        }
        sG = ap;        // total positives
        sD0 = an;       // total negatives
        (void)sD0;
    }
    __syncthreads();
    const float G = sG;
    float jacsum = 0.0f;
    if (G > 0.0f) {
        float C = ep[j], D = en[j];
        for (int k = P3_BPT - 1; k >= 0; k--) {
            int bin = lo + k;
            C += (float)hp[bin];
            D += (float)hn[bin];
            float jac = 1.0f - __fdividef(G - C, G + D);
            if (bin >= 1) jacsum += jac;
        }
    }
    // block reduce
    #pragma unroll
    for (int off = 16; off; off >>= 1)
        jacsum += __shfl_down_sync(0xffffffffu, jacsum, off);
    if ((j & 31) == 0) atomicAdd(&s_jacsum, jacsum);
    __syncthreads();
    if (j == 0) {
        float lov = (G > 0.0f) ? WBIN * (0.5f + s_jacsum) : 0.0f;
        g_lov[b][n] = lov;
    }
}

// ---------------- final assembly ----------------
__global__ void final_kernel(float* __restrict__ out) {
    __shared__ float parts[BB];
    int b = threadIdx.x;
    if (b < BB) {
        float npres = 0.0f, lovs = 0.0f, sls = 0.0f, fgs = 0.0f;
        #pragma unroll
        for (int n = 0; n < NI; n++) {
            float cnt = g_sums[b][n][0];
            float pres = (cnt > 0.0f) ? 1.0f : 0.0f;
            float safe = fmaxf(cnt, 1.0f);
            npres += pres;
            lovs += pres * g_lov[b][n];
            sls  += pres * g_sl[b][n] / safe;
            fgs  += pres * g_fg[b][n] / safe;
        }
        float np = fmaxf(npres, 1.0f);
        float lov_b = lovs / np;
        float sig_b = sls / np;
        float bgc = fmaxf(g_bg[b][0], 1.0f);
        float bgl = g_bg[b][1] / bgc;
        float seed_b = (bgl + fgs) / (1.0f + npres);
        parts[b] = lov_b + sig_b + seed_b;
    }
    __syncthreads();
    if (threadIdx.x == 0)
        out[0] = (parts[0] + parts[1] + parts[2] + parts[3]) * 0.25f;
}

// ---------------- launch ----------------
extern "C" void kernel_launch(void* const* d_in, const int* in_sizes, int n_in,
                              void* d_out, int out_size) {
    const float* xv    = (const float*)d_in[0];   // [4,2,512,1024]
    const float* xs    = (const float*)d_in[1];   // [4,2,512,1024]
    const float* xseed = (const float*)d_in[2];   // [4,1,512,1024]
    const int*   t     = (const int*)d_in[3];     // [4,512,1024]
    float* out = (float*)d_out;

    zero_kernel<<<1024, 1024>>>();

    dim3 g1(HW / (P1_TPB * P1_PPT), BB);   // (64, 4)
    pass1_kernel<<<g1, P1_TPB>>>(xv, xs, xseed, t);

    finalize_stats_kernel<<<1, 32>>>();

    dim3 g2(HW / (P2_TPB * P2_PPT), BB);   // (256, 4)
    pass2_kernel<<<g2, P2_TPB>>>(xv, xs, xseed, t);

    pass3_kernel<<<NI * BB, P3_TPB>>>();

    final_kernel<<<1, 32>>>(out);
}

// round 2
// speedup vs baseline: 2.3160x; 2.3160x over previous
#include <cuda_runtime.h>
#include <cstdint>

// Problem constants
#define BB 4
#define WW 1024
#define HW (512*1024)       // pixels per batch image
#define NI 8                // instances 1..8
#define NBINS 8192
#define WBIN (2.0f/(float)NBINS)
#define NTILE1 64
#define LAMBDA 0.72134752044448170f   // 0.5*log2(e)
#define INV1024 (1.0f/1024.0f)

// ---------------- device scratch ----------------
__device__ unsigned int g_hist[NI*BB*2*NBINS];     // 2 MB: [n][b][pos][bin]
__device__ float g_part[NI][BB][NTILE1][5];        // pass1 partials (cnt,e0,e1,q0,q1)
__device__ float g_coef[BB][NI][8];                // a0,b0,a1,b1,k,pp0,pp1,cnt
__device__ float g_sl[BB][NI];
__device__ float g_fg[BB][NI];
__device__ float g_bg[BB][2];
__device__ float g_lov[BB][NI];

// ---------------- fast tanh (Eigen-style rational, |err| ~1e-7) ----------------
__device__ __forceinline__ float tanh_fast(float x) {
    float xc = fminf(fmaxf(x, -7.99881172f), 7.99881172f);
    float x2 = xc * xc;
    float p = fmaf(x2, -2.76076847742355e-16f, 2.00018790482477e-13f);
    p = fmaf(x2, p, -8.60467152213735e-11f);
    p = fmaf(x2, p, 5.12229709037114e-08f);
    p = fmaf(x2, p, 1.48572235717979e-05f);
    p = fmaf(x2, p, 6.37261928875436e-04f);
    p = fmaf(x2, p, 4.89352455891786e-03f);
    p = p * xc;
    float q = fmaf(x2, 1.19825839466702e-06f, 1.18534705686654e-04f);
    q = fmaf(x2, q, 2.26843463243900e-03f);
    q = fmaf(x2, q, 4.89352518554385e-03f);
    return __fdividef(p, q);
}

// ---------------- pass 1: per (b, instance-group) masked sums + hist zero ----------------
#define P1_TPB 256
#define P1_PPT 32   // 8192 px/block -> 64 blocks/batch per group

__global__ __launch_bounds__(P1_TPB)
void pass1_kernel(const float* __restrict__ xv, const float* __restrict__ xs,
                  const int* __restrict__ t) {
    const int b = blockIdx.y;
    const int grp = blockIdx.z;              // instances 4*grp+1 .. 4*grp+4
    const int bx = blockIdx.x;
    const float* xv0 = xv + (long)b*2*HW;
    const float* xv1 = xv0 + HW;
    const float* xs0 = xs + (long)b*2*HW;
    const float* xs1 = xs0 + HW;
    const int*   tp  = t + (long)b*HW;

    float a[4][5];
    #pragma unroll
    for (int j = 0; j < 4; j++)
        #pragma unroll
        for (int i = 0; i < 5; i++) a[j][i] = 0.0f;

    const int p0 = bx * (P1_TPB * P1_PPT) + threadIdx.x;
    #pragma unroll 4
    for (int i = 0; i < P1_PPT; i++) {
        int p = p0 + i * P1_TPB;
        int tv = tp[p];
        unsigned rel = (unsigned)(tv - 1 - 4*grp);
        if (rel < 4u) {
            float e0 = tanh_fast(xv0[p]) + (float)(p >> 10) * INV1024;
            float e1 = tanh_fast(xv1[p]) + (float)(p & 1023) * INV1024;
            float q0 = xs0[p], q1 = xs1[p];
            #pragma unroll
            for (int j = 0; j < 4; j++) {
                float m = (rel == (unsigned)j) ? 1.0f : 0.0f;
                a[j][0] += m;
                a[j][1] = fmaf(m, e0, a[j][1]);
                a[j][2] = fmaf(m, e1, a[j][2]);
                a[j][3] = fmaf(m, q0, a[j][3]);
                a[j][4] = fmaf(m, q1, a[j][4]);
            }
        }
    }
    // warp reduce 20 values
    #pragma unroll
    for (int off = 16; off; off >>= 1)
        #pragma unroll
        for (int j = 0; j < 4; j++)
            #pragma unroll
            for (int i = 0; i < 5; i++)
                a[j][i] += __shfl_down_sync(0xffffffffu, a[j][i], off);

    __shared__ float sacc[20];
    if (threadIdx.x < 20) sacc[threadIdx.x] = 0.0f;
    __syncthreads();
    if ((threadIdx.x & 31) == 0) {
        #pragma unroll
        for (int j = 0; j < 4; j++)
            #pragma unroll
            for (int i = 0; i < 5; i++)
                atomicAdd(&sacc[j*5+i], a[j][i]);
    }
    __syncthreads();
    if (threadIdx.x < 20)
        g_part[4*grp + threadIdx.x/5][b][bx][threadIdx.x % 5] = sacc[threadIdx.x];

    // zero histogram: 131072 threads total, 524288 words -> 4 each, coalesced
    int gid = (((int)blockIdx.z * BB + b) * NTILE1 + bx) * P1_TPB + threadIdx.x;
    g_hist[gid]          = 0u;
    g_hist[gid + 131072] = 0u;
    g_hist[gid + 262144] = 0u;
    g_hist[gid + 393216] = 0u;
}

// ---------------- finalize: reduce partials -> coefficients ----------------
__global__ __launch_bounds__(1024)
void finalize_kernel() {
    int tid = threadIdx.x;
    int w = tid >> 5, l = tid & 31;     // 32 warps = 32 (n,b) rows
    int n = w >> 2, b = w & 3;
    float s[5];
    #pragma unroll
    for (int i = 0; i < 5; i++)
        s[i] = g_part[n][b][l][i] + g_part[n][b][l + 32][i];
    #pragma unroll
    for (int off = 16; off; off >>= 1)
        #pragma unroll
        for (int i = 0; i < 5; i++)
            s[i] += __shfl_down_sync(0xffffffffu, s[i], off);
    if (l == 0) {
        float cnt = s[0];
        float inv = 1.0f / fmaxf(cnt, 1.0f);
        float c0 = s[1]*inv, c1 = s[2]*inv, pp0 = s[3]*inv, pp1 = s[4]*inv;
        float ps0 = expf(10.0f * pp0), ps1 = expf(10.0f * pp1);
        g_coef[b][n][0] = -LAMBDA * ps0;
        g_coef[b][n][1] = 2.0f * LAMBDA * ps0 * c0;
        g_coef[b][n][2] = -LAMBDA * ps1;
        g_coef[b][n][3] = 2.0f * LAMBDA * ps1 * c1;
        g_coef[b][n][4] = 13.0f - LAMBDA * (ps0*c0*c0 + ps1*c1*c1);
        g_coef[b][n][5] = pp0;
        g_coef[b][n][6] = pp1;
        g_coef[b][n][7] = cnt;
    }
    if (tid < 32) { ((float*)g_sl)[tid] = 0.0f; ((float*)g_fg)[tid] = 0.0f; }
    if (tid < 8)  ((float*)g_bg)[tid] = 0.0f;
}

// ---------------- pass 2: histograms + sigma/seed partials ----------------
#define P2_TPB 256
#define P2_PPT 8    // 2048 px/block -> 256 blocks/batch

__global__ __launch_bounds__(P2_TPB)
void pass2_kernel(const float* __restrict__ xv, const float* __restrict__ xs,
                  const float* __restrict__ xseed, const int* __restrict__ t) {
    const int b = blockIdx.y;
    const int tid = threadIdx.x;
    const int wid = tid >> 5;

    __shared__ float sa0[NI], sb0[NI], sa1[NI], sb1[NI], sk[NI];
    __shared__ float spp0[NI+1], spp1[NI+1];
    __shared__ float s_sl[8][NI+1], s_fg[8][NI+1];
    __shared__ float sbg[2];
    if (tid < NI) {
        sa0[tid] = g_coef[b][tid][0];
        sb0[tid] = g_coef[b][tid][1];
        sa1[tid] = g_coef[b][tid][2];
        sb1[tid] = g_coef[b][tid][3];
        sk[tid]  = g_coef[b][tid][4];
        spp0[tid+1] = g_coef[b][tid][5];
        spp1[tid+1] = g_coef[b][tid][6];
    }
    if (tid == NI) { spp0[0] = 0.0f; spp1[0] = 0.0f; }
    if (tid < 8*(NI+1)) { ((float*)s_sl)[tid] = 0.0f; ((float*)s_fg)[tid] = 0.0f; }
    if (tid < 2) sbg[tid] = 0.0f;
    __syncthreads();

    const float* xv0 = xv + (long)b*2*HW;
    const float* xv1 = xv0 + HW;
    const float* xs0 = xs + (long)b*2*HW;
    const float* xs1 = xs0 + HW;
    const float* sdp = xseed + (long)b*HW;
    const int*   tp  = t + (long)b*HW;

    float bgc = 0.0f, bgs = 0.0f;
    const int p0 = blockIdx.x * (P2_TPB * P2_PPT) + tid;

    for (int i = 0; i < P2_PPT; i++) {
        int p = p0 + i * P2_TPB;
        int tv = tp[p];
        float e0 = tanh_fast(xv0[p]) + (float)(p >> 10) * INV1024;
        float e1 = tanh_fast(xv1[p]) + (float)(p & 1023) * INV1024;
        float E0 = e0*e0, E1 = e1*e1;
        float q0 = xs0[p], q1 = xs1[p];
        float sd = fmaf(tanh_fast(0.5f * sdp[p]), 0.5f, 0.5f);
        float isbg = (tv == 0) ? 1.0f : 0.0f;
        bgc += isbg;
        bgs = fmaf(isbg, sd*sd, bgs);

        float yown = 0.0f;
        #pragma unroll
        for (int n = 0; n < NI; n++) {
            // u = 13 - 0.5*log2e * dist   ->  y = 2^u = 8192 * gauss
            float u = fmaf(sa0[n], E0, fmaf(sb0[n], e0, fmaf(sa1[n], E1, fmaf(sb1[n], e1, sk[n]))));
            float um = fmaxf(u, -2.0f);
            float fr = um + 12582912.0f;           // round-to-nearest int
            float f  = um - (fr - 12582912.0f);    // f in [-0.5, 0.5]
            int   ib = __float_as_int(fr);
            float scale = __int_as_float((ib + (127 - 0x4B400000)) << 23); // 2^i
            float pe = fmaf(f, 1.33335581e-3f, 9.61812911e-3f);
            pe = fmaf(f, pe, 5.55041087e-2f);
            pe = fmaf(f, pe, 2.40226507e-1f);
            pe = fmaf(f, pe, 6.93147181e-1f);
            pe = fmaf(f, pe, 1.0f);
            float y = pe * scale;                  // = 8192*gauss, in [0.25, 8192]
            bool pos = (tv == n + 1);
            if (pos) yown = y;
            float binf = pos ? (8192.0f - y) : y;  // err * BSCALE
            int bin = (int)binf;
            bin = min(bin, NBINS - 1);
            bin = max(bin, 0);
            int off = ((n*BB + b)*2 + (pos ? 1 : 0))*NBINS + bin;
            atomicAdd(&g_hist[off], 1u);
        }
        // own-instance sigma/seed terms (tv-indexed; slot 0 is a dummy)
        float dd0 = q0 - spp0[tv];
        float dd1 = q1 - spp1[tv];
        float vsl = dd0*dd0 + dd1*dd1;
        float gown = yown * (1.0f/8192.0f);
        float fgd = sd - gown;
        float vfg = fgd*fgd;
        if (tv > 0) {
            atomicAdd(&s_sl[wid][tv], vsl);
            atomicAdd(&s_fg[wid][tv], vfg);
        }
    }
    __syncthreads();   // s_sl/s_fg complete

    // bg reduce
    #pragma unroll
    for (int off = 16; off; off >>= 1) {
        bgc += __shfl_down_sync(0xffffffffu, bgc, off);
        bgs += __shfl_down_sync(0xffffffffu, bgs, off);
    }
    if ((tid & 31) == 0) {
        atomicAdd(&sbg[0], bgc);
        atomicAdd(&sbg[1], bgs);
    }
    // sl/fg block reduce -> global
    if (tid >= 32 && tid < 32 + NI) {
        int n = tid - 32;
        float ssl = 0.0f, sfg = 0.0f;
        #pragma unroll
        for (int w = 0; w < 8; w++) { ssl += s_sl[w][n+1]; sfg += s_fg[w][n+1]; }
        atomicAdd(&g_sl[b][n], ssl);
        atomicAdd(&g_fg[b][n], sfg);
    }
    __syncthreads();
    if (tid == 0) {
        atomicAdd(&g_bg[b][0], sbg[0]);
        atomicAdd(&g_bg[b][1], sbg[1]);
    }
}

// ---------------- pass 3: histogram suffix scan -> lovasz ----------------
#define P3_TPB 256
#define P3_BPT (NBINS / P3_TPB)   // 32

__global__ __launch_bounds__(P3_TPB)
void pass3_kernel() {
    const int row = blockIdx.x;    // 0..31
    const int n = row >> 2;
    const int b = row & 3;
    const unsigned int* hp = g_hist + (long)((n*BB + b)*2 + 1)*NBINS;
    const unsigned int* hn = g_hist + (long)((n*BB + b)*2 + 0)*NBINS;
    const int j = threadIdx.x;
    const int lo = j * P3_BPT;

    float lp = 0.0f, ln = 0.0f;
    #pragma unroll 8
    for (int k = 0; k < P3_BPT; k++) { lp += (float)hp[lo+k]; ln += (float)hn[lo+k]; }

    __shared__ float sp[P3_TPB], sn[P3_TPB], ep[P3_TPB], en[P3_TPB];
    __shared__ float sG, s_jacsum;
    sp[j] = lp; sn[j] = ln;
    if (j == 0) s_jacsum = 0.0f;
    __syncthreads();
    if (j == 0) {
        float ap = 0.0f, an = 0.0f;
        for (int k = P3_TPB - 1; k >= 0; k--) {
            ep[k] = ap; en[k] = an;
            ap += sp[k]; an += sn[k];
        }
        sG = ap;
    }
    __syncthreads();
    const float G = sG;
    float jacsum = 0.0f;
    if (G > 0.0f) {
        float C = ep[j], D = en[j];
        for (int k = P3_BPT - 1; k >= 0; k--) {
            int bin = lo + k;
            C += (float)hp[bin];
            D += (float)hn[bin];
            float jac = 1.0f - __fdividef(G - C, G + D);
            if (bin >= 1) jacsum += jac;
        }
    }
    #pragma unroll
    for (int off = 16; off; off >>= 1)
        jacsum += __shfl_down_sync(0xffffffffu, jacsum, off);
    if ((j & 31) == 0) atomicAdd(&s_jacsum, jacsum);
    __syncthreads();
    if (j == 0)
        g_lov[b][n] = (G > 0.0f) ? WBIN * (0.5f + s_jacsum) : 0.0f;
}

// ---------------- final assembly ----------------
__global__ void final_kernel(float* __restrict__ out) {
    __shared__ float parts[BB];
    int b = threadIdx.x;
    if (b < BB) {
        float npres = 0.0f, lovs = 0.0f, sls = 0.0f, fgs = 0.0f;
        #pragma unroll
        for (int n = 0; n < NI; n++) {
            float cnt = g_coef[b][n][7];
            float pres = (cnt > 0.0f) ? 1.0f : 0.0f;
            float inv = 1.0f / fmaxf(cnt, 1.0f);
            npres += pres;
            lovs += pres * g_lov[b][n];
            sls  += pres * g_sl[b][n] * inv;
            fgs  += pres * g_fg[b][n] * inv;
        }
        float np = fmaxf(npres, 1.0f);
        float bgc = fmaxf(g_bg[b][0], 1.0f);
        float bgl = g_bg[b][1] / bgc;
        parts[b] = lovs / np + sls / np + (bgl + fgs) / (1.0f + npres);
    }
    __syncthreads();
    if (threadIdx.x == 0)
        out[0] = (parts[0] + parts[1] + parts[2] + parts[3]) * 0.25f;
}

// ---------------- launch ----------------
extern "C" void kernel_launch(void* const* d_in, const int* in_sizes, int n_in,
                              void* d_out, int out_size) {
    const float* xv    = (const float*)d_in[0];   // [4,2,512,1024]
    const float* xs    = (const float*)d_in[1];   // [4,2,512,1024]
    const float* xseed = (const float*)d_in[2];   // [4,1,512,1024]
    const int*   t     = (const int*)d_in[3];     // [4,512,1024]
    float* out = (float*)d_out;

    dim3 g1(NTILE1, BB, 2);
    pass1_kernel<<<g1, P1_TPB>>>(xv, xs, t);

    finalize_kernel<<<1, 1024>>>();

    dim3 g2(HW / (P2_TPB * P2_PPT), BB);   // (256, 4)
    pass2_kernel<<<g2, P2_TPB>>>(xv, xs, xseed, t);

    pass3_kernel<<<NI * BB, P3_TPB>>>();

    final_kernel<<<1, 32>>>(out);
}